// round 8
// baseline (speedup 1.0000x reference)
#include <cuda_runtime.h>
#include <math.h>

// Problem constants
#define TT   1024
#define BB   64
#define INF  256
#define HH   512
#define OUTF 256
#define G3   1536           // 3*H
#define BH   (BB*HH)        // 32768
#define BH3  (BB*G3)        // 98304
#define NCTA 128            // recurrence grid (<= 148 SMs -> all co-resident)
#define WPAD 520            // padded row stride (floats) for weight smem

// ---------------- scratch (no allocations allowed) ----------------
__device__ float    g_gi[(size_t)TT * BH3];   // [T,B,3H] input-side gate projections
__device__ float    g_h[2 * BH];              // double-buffered hidden state
__device__ unsigned g_bar;                    // grid-barrier arrival counter

// ---------------- f32x2 helpers (FFMA2: full-rate fp32 on sm_10x) -----
__device__ __forceinline__ void fma2(unsigned long long& acc,
                                     unsigned long long a,
                                     unsigned long long b) {
    asm("fma.rn.f32x2 %0, %1, %2, %0;" : "+l"(acc) : "l"(a), "l"(b));
}
__device__ __forceinline__ unsigned long long dupf(float x) {
    unsigned long long r;
    asm("mov.b64 %0, {%1, %1};" : "=l"(r) : "r"(__float_as_uint(x)));
    return r;
}

// =====================================================================
// Kernel 1: gi[t,b,g] = sum_i x[b,t,i] * W_ih[g,i] + b_ih[g]
// GEMM: M = T*B (row m = t*64 + b), N = 1536, K = 256
// =====================================================================
__global__ __launch_bounds__(256) void gi_gemm_kernel(
    const float* __restrict__ x,
    const float* __restrict__ wih,
    const float* __restrict__ bih,
    float* __restrict__ gi)
{
    __shared__ float As[16 * 132];   // [k][m]
    __shared__ float Bs[16 * 68];    // [k][n]

    const int tid = threadIdx.x;
    const int m0  = blockIdx.y * 128;
    const int n0  = blockIdx.x * 64;
    const int ty  = tid >> 4;
    const int tx  = tid & 15;

    unsigned long long acc[4][4];
    #pragma unroll
    for (int i = 0; i < 4; i++)
        #pragma unroll
        for (int j = 0; j < 4; j++) acc[i][j] = 0ULL;

    for (int k0 = 0; k0 < INF; k0 += 16) {
        #pragma unroll
        for (int it = 0; it < 2; it++) {
            int L  = tid + it * 256;
            int r  = L >> 2;
            int kq = L & 3;
            int m  = m0 + r;
            int t  = m >> 6;
            int b  = m & 63;
            float4 v = *reinterpret_cast<const float4*>(
                &x[((size_t)b * TT + t) * INF + k0 + kq * 4]);
            As[(kq * 4 + 0) * 132 + r] = v.x;
            As[(kq * 4 + 1) * 132 + r] = v.y;
            As[(kq * 4 + 2) * 132 + r] = v.z;
            As[(kq * 4 + 3) * 132 + r] = v.w;
        }
        {
            int n  = tid >> 2;
            int kq = tid & 3;
            float4 v = *reinterpret_cast<const float4*>(
                &wih[(size_t)(n0 + n) * INF + k0 + kq * 4]);
            Bs[(kq * 4 + 0) * 68 + n] = v.x;
            Bs[(kq * 4 + 1) * 68 + n] = v.y;
            Bs[(kq * 4 + 2) * 68 + n] = v.z;
            Bs[(kq * 4 + 3) * 68 + n] = v.w;
        }
        __syncthreads();

        #pragma unroll
        for (int k = 0; k < 16; k++) {
            const ulonglong2* ap =
                reinterpret_cast<const ulonglong2*>(&As[k * 132 + ty * 8]);
            ulonglong2 a01 = ap[0];
            ulonglong2 a23 = ap[1];
            float4 bv = *reinterpret_cast<const float4*>(&Bs[k * 68 + tx * 4]);
            unsigned long long bd[4] = {dupf(bv.x), dupf(bv.y), dupf(bv.z), dupf(bv.w)};
            unsigned long long ap4[4] = {a01.x, a01.y, a23.x, a23.y};
            #pragma unroll
            for (int i = 0; i < 4; i++)
                #pragma unroll
                for (int j = 0; j < 4; j++)
                    fma2(acc[i][j], ap4[i], bd[j]);
        }
        __syncthreads();
    }

    #pragma unroll
    for (int i = 0; i < 4; i++) {
        int mA = m0 + ty * 8 + 2 * i;
        #pragma unroll
        for (int j = 0; j < 4; j++) {
            int n = n0 + tx * 4 + j;
            float2 v = *reinterpret_cast<float2*>(&acc[i][j]);
            float bb = bih[n];
            gi[(size_t)mA * G3 + n]       = v.x + bb;
            gi[(size_t)(mA + 1) * G3 + n] = v.y + bb;
        }
    }
}

// =====================================================================
// Kernel 2: persistent GRU recurrence. 128 CTAs x 256 threads.
// CTA cb owns hidden columns j0=cb*4..j0+3 (all 3 gates = 12 W rows).
// Thread t: q = t&7 (k-phase), bp = t>>3 (0..31), batches {bp, bp+32}.
// h streamed from L2 with DEPTH-3 register prefetch (4 buffers; loop is
// fully unrolled so indices are static). Weights in SMEM (broadcast
// wavefronts). xor4-first butterfly (48 shuffles). Grid barrier:
// release-atomic arrive + acquire poll (no L1 flush).
// =====================================================================
__global__ __launch_bounds__(256, 1) void gru_recur_kernel(
    const float* __restrict__ whh,
    const float* __restrict__ bhh,
    const float* __restrict__ gi,
    float* __restrict__ outs)   // may be nullptr
{
    __shared__ float w_sh[12 * WPAD];   // ~25 KB

    const int tid = threadIdx.x;
    const int cb  = blockIdx.x;
    const int j0  = cb * 4;
    const int q   = tid & 7;           // k-phase 0..7
    const int bp  = tid >> 3;          // 0..31 -> batches {bp, bp+32}
    const int jj  = q & 3;             // owned column offset
    const int wb  = q >> 2;            // owned batch selector
    const int bown = bp + (wb << 5);
    const int j    = j0 + jj;

    // Load this CTA's 12 W_hh rows into shared (once).
    for (int idx = tid; idx < 12 * 512; idx += 256) {
        int row = idx >> 9;            // 0..11  (gate*4 + jr)
        int k   = idx & 511;
        int g   = row >> 2;
        int jr  = row & 3;
        w_sh[row * WPAD + k] = whh[((size_t)g * HH + j0 + jr) * HH + k];
    }
    const float bh_r = bhh[j];
    const float bh_z = bhh[HH + j];
    const float bh_n = bhh[2 * HH + j];
    float hreg = 0.f;                  // h_prev(bown, j) lives here
    __syncthreads();

    // gi for t=0 (current-step registers)
    float g_r, g_z, g_n;
    {
        const float* gib = gi + (size_t)bown * G3 + j;
        g_r = __ldg(gib); g_z = __ldg(gib + HH); g_n = __ldg(gib + 2 * HH);
    }

    unsigned long long bar_addr;
    asm("cvta.global.u64 %0, %1;" : "=l"(bar_addr) : "l"(&g_bar));

    for (int t = 0; t < TT; t++) {
        const float* hA = g_h + (t & 1) * BH + (size_t)bp * HH;         // batch bp
        const float* hB = hA + 32 * HH;                                  // batch bp+32
        float*       hnxt = g_h + ((t + 1) & 1) * BH;

        unsigned long long accA[12], accB[12];
        #pragma unroll
        for (int r = 0; r < 12; r++) { accA[r] = 0ULL; accB[r] = 0ULL; }

        // Depth-3 prefetch ring (4 buffers). Loop fully unrolled ->
        // (xi & 3) indices are compile-time constants.
        float4 bufA[4], bufB[4];
        #pragma unroll
        for (int p = 0; p < 3; p++) {
            bufA[p] = __ldcg(reinterpret_cast<const float4*>(hA + p * 32 + 4 * q));
            bufB[p] = __ldcg(reinterpret_cast<const float4*>(hB + p * 32 + 4 * q));
        }

        #pragma unroll
        for (int xi = 0; xi < 16; xi++) {
            if (xi < 13) {
                bufA[(xi + 3) & 3] = __ldcg(reinterpret_cast<const float4*>(
                    hA + (xi + 3) * 32 + 4 * q));
                bufB[(xi + 3) & 3] = __ldcg(reinterpret_cast<const float4*>(
                    hB + (xi + 3) * 32 + 4 * q));
            }
            ulonglong2 ha = *reinterpret_cast<ulonglong2*>(&bufA[xi & 3]);
            ulonglong2 hb = *reinterpret_cast<ulonglong2*>(&bufB[xi & 3]);
            const int base = xi * 32 + 4 * q;
            #pragma unroll
            for (int r = 0; r < 12; r++) {
                ulonglong2 w2 = *reinterpret_cast<const ulonglong2*>(
                    &w_sh[r * WPAD + base]);
                fma2(accA[r], ha.x, w2.x); fma2(accA[r], ha.y, w2.y);
                fma2(accB[r], hb.x, w2.x); fma2(accB[r], hb.y, w2.y);
            }
        }

        // Prefetch NEXT step's gi into separate registers (latency overlaps
        // the reduction + barrier). Committed to g_* only after gate math.
        float n_r, n_z, n_n;
        {
            int tn = (t + 1 < TT) ? (t + 1) : t;
            const float* gib = gi + (size_t)tn * BH3 + (size_t)bown * G3 + j;
            n_r = __ldg(gib);
            n_z = __ldg(gib + HH);
            n_n = __ldg(gib + 2 * HH);
        }

        // Fold f32x2 halves.
        float sA[12], sB[12];
        #pragma unroll
        for (int r = 0; r < 12; r++) {
            float2 fa = *reinterpret_cast<float2*>(&accA[r]);
            float2 fb = *reinterpret_cast<float2*>(&accB[r]);
            sA[r] = fa.x + fa.y;
            sB[r] = fb.x + fb.y;
        }
        // xor4 round: pair (q, q^4) partial-sums for both batch arrays.
        #pragma unroll
        for (int r = 0; r < 12; r++) {
            sA[r] += __shfl_xor_sync(0xffffffffu, sA[r], 4);
            sB[r] += __shfl_xor_sync(0xffffffffu, sB[r], 4);
        }
        // Merge: low lanes (wb=0) carry sA pairsums, high lanes carry sB.
        float m[12];
        #pragma unroll
        for (int r = 0; r < 12; r++) m[r] = wb ? sB[r] : sA[r];
        // Butterflies within each 4-lane group (xor1, xor2 stay in-group).
        #pragma unroll
        for (int d = 1; d <= 2; d <<= 1) {
            #pragma unroll
            for (int r = 0; r < 12; r++)
                m[r] += __shfl_xor_sync(0xffffffffu, m[r], d);
        }
        float hr = (jj == 0) ? m[0] : (jj == 1) ? m[1] : (jj == 2) ? m[2]  : m[3];
        float hz = (jj == 0) ? m[4] : (jj == 1) ? m[5] : (jj == 2) ? m[6]  : m[7];
        float hn = (jj == 0) ? m[8] : (jj == 1) ? m[9] : (jj == 2) ? m[10] : m[11];

        // Gate math (torch GRU order r, z, n) — uses CURRENT step's gi.
        float rr = 1.f / (1.f + __expf(-(g_r + bh_r + hr)));
        float zz = 1.f / (1.f + __expf(-(g_z + bh_z + hz)));
        float nn = tanhf(g_n + rr * (hn + bh_n));
        float hnew = nn + zz * (hreg - nn);    // (1-z)*n + z*h
        hreg = hnew;

        // Commit prefetched gi for the next iteration.
        g_r = n_r; g_z = n_z; g_n = n_n;

        __stcg(&hnxt[(size_t)bown * HH + j], hnew);
        if (outs) __stcg(&outs[(size_t)t * BH + (size_t)bown * HH + j], hnew);

        // Grid barrier: release-arrive + acquire-poll (no L1 flush).
        __syncthreads();
        if (tid == 0) {
            unsigned oldv;
            asm volatile("atom.release.gpu.global.add.u32 %0, [%1], 1;"
                         : "=r"(oldv) : "l"(bar_addr) : "memory");
            const unsigned target = (unsigned)(t + 1) * NCTA;
            unsigned v;
            do {
                asm volatile("ld.acquire.gpu.global.u32 %0, [%1];"
                             : "=r"(v) : "l"(bar_addr) : "memory");
            } while (v < target);
        }
        __syncthreads();
    }
}

// =====================================================================
// Kernel 3: out[b,o] = h_final[b,:] . fc_w[o,:] + fc_b[o]
// =====================================================================
__global__ __launch_bounds__(256) void fc_kernel(
    const float* __restrict__ hsrc,
    const float* __restrict__ fcw,
    const float* __restrict__ fcb,
    float* __restrict__ out)
{
    __shared__ float hrow[HH];
    const int b = blockIdx.x;
    const int o = threadIdx.x;
    for (int i = threadIdx.x; i < HH; i += 256)
        hrow[i] = hsrc[(size_t)b * HH + i];
    __syncthreads();

    float acc = fcb[o];
    const float4* w4 = reinterpret_cast<const float4*>(fcw + (size_t)o * HH);
    #pragma unroll 8
    for (int k4 = 0; k4 < HH / 4; k4++) {
        float4 w = w4[k4];
        acc = fmaf(hrow[k4 * 4 + 0], w.x, acc);
        acc = fmaf(hrow[k4 * 4 + 1], w.y, acc);
        acc = fmaf(hrow[k4 * 4 + 2], w.z, acc);
        acc = fmaf(hrow[k4 * 4 + 3], w.w, acc);
    }
    out[(size_t)b * OUTF + o] = acc;
}

// Kernel 4: hn = final h ; h0 = zeros
__global__ void tail_kernel(const float* __restrict__ hsrc,
                            float* __restrict__ dst_hn,
                            float* __restrict__ dst_h0,
                            int write_hn, int write_h0)
{
    int i = blockIdx.x * blockDim.x + threadIdx.x;
    if (i < BH) {
        if (write_hn) dst_hn[i] = hsrc[i];
        if (write_h0) dst_h0[i] = 0.f;
    }
}

// Profiling positioner: keeps ncu "-s 5 -c 1" landing on gru_recur_kernel
// (order: memset, memset, dummy, dummy, gi, recur).
__global__ void dummy_kernel() {}

// =====================================================================
extern "C" void kernel_launch(void* const* d_in, const int* in_sizes, int n_in,
                              void* d_out, int out_size)
{
    const float* x   = (const float*)d_in[0];
    const float* wih = (const float*)d_in[1];
    const float* whh = (const float*)d_in[2];
    const float* bih = (const float*)d_in[3];
    const float* bhh = (const float*)d_in[4];
    const float* fcw = (const float*)d_in[5];
    const float* fcb = (const float*)d_in[6];
    float* out = (float*)d_out;

    void *p_h = nullptr, *p_bar = nullptr, *p_gi = nullptr;
    cudaGetSymbolAddress(&p_h,  g_h);
    cudaGetSymbolAddress(&p_bar, g_bar);
    cudaGetSymbolAddress(&p_gi, g_gi);

    // Reset recurrence state each invocation (capturable, deterministic).
    cudaMemsetAsync(p_h,  0, sizeof(float) * 2 * BH, 0);
    cudaMemsetAsync(p_bar, 0, sizeof(unsigned), 0);

    dummy_kernel<<<1, 32>>>();
    dummy_kernel<<<1, 32>>>();

    // Phase 1: input-side projections
    dim3 gg(G3 / 64, (TT * BB) / 128);   // (24, 512)
    gi_gemm_kernel<<<gg, 256>>>(x, wih, bih, (float*)p_gi);

    // Output layout: concatenation of (outs[T,B,H], out[B,OUT], hn[B,H], h0[B,H])
    const long long OUTS_N = (long long)TT * BH;
    long long remaining = (long long)out_size;
    float* outs_dst = nullptr;
    long long off = 0;
    if (remaining >= OUTS_N) { outs_dst = out; off = OUTS_N; }

    // Phase 2: recurrence (final h lands in g_h[0..BH) since T is even)
    gru_recur_kernel<<<NCTA, 256>>>(whh, bhh, (const float*)p_gi, outs_dst);

    const float* hfinal = (const float*)p_h;

    // Phase 3: epilogue outputs
    if (remaining - off >= (long long)BB * OUTF) {
        fc_kernel<<<BB, 256>>>(hfinal, fcw, fcb, out + off);
        off += (long long)BB * OUTF;
    } else if (remaining == (long long)BB * OUTF) {
        fc_kernel<<<BB, 256>>>(hfinal, fcw, fcb, out);
        off = remaining;
    }
    int wh = (remaining - off >= (long long)BH) ? 1 : 0;
    int w0 = (remaining - off >= (long long)2 * BH) ? 1 : 0;
    if (wh) {
        tail_kernel<<<(BH + 255) / 256, 256>>>(hfinal,
                                               out + off,
                                               out + off + BH,
                                               wh, w0);
    }
}